// round 2
// baseline (speedup 1.0000x reference)
#include <cuda_runtime.h>
#include <math.h>

#define NB 4
#define NL 4096
#define DIMQ 7168
#define NH 128
#define NK 128
#define DC 512
#define DCQ 1536
#define NR 64

// ---------------- scratch (static device globals; no allocation) ----------------
__device__ float g_qhk[NB * NH * NK];       // [B][16384]
__device__ float g_qbig[NB * NH * DCQ];     // [B][H][1536]
__device__ float g_qr[NB * NH * NR];        // [B][H][64]
__device__ float g_vq[NB * DC * NH];        // [B][512][128]  (d-major for scores tiling)
__device__ float g_kv[NB * NL * DC];        // RoPE'd kv cache
__device__ float g_sc[NB * NH * NL];        // scores -> attn (in place)
__device__ float g_part[8 * NB * NH * DC];  // ctx partials over l-splits
__device__ float g_ctxc[NB * NH * DC];
__device__ float g_ctxlat[NB * NH * NK];    // [B][16384]
__device__ float g_invf[256];

// ---------------- inv-freq table (double exp, rounded to fp32) ----------------
__global__ void k_init_invf() {
    int t = threadIdx.x;
    // inv_freq[t] = 10000^(-t/256)
    g_invf[t] = (float)exp(-9.210340371976184 * (double)t / 256.0);
}

// ---------------- RoPE: kv = kv_c*cos + rotate_half(kv_c)*sin ----------------
__global__ void k_rope(const float* __restrict__ kvc) {
    int bl = blockIdx.x;            // b*L + l
    int l = bl & (NL - 1);
    const float* x = kvc + (size_t)bl * DC;
    float* y = g_kv + (size_t)bl * DC;
    int d = threadIdx.x;            // 0..255
    float x1 = x[d], x2 = x[d + 256];
    int j = d >> 1;
    float th1 = (float)l * g_invf[j];
    float th2 = (float)l * g_invf[128 + j];
    float s1, c1, s2, c2;
    sincosf(th1, &s1, &c1);
    sincosf(th2, &s2, &c2);
    y[d]       = x1 * c1 - x2 * s1;   // rotate_half: first half uses -x[d+256]
    y[d + 256] = x2 * c2 + x1 * s2;   // second half uses +x[d-256]
}

// ---------------- generic 4-row GEMV: Y[b,row] = dot(X[b,:], W[row,:]) ----------------
// warp-per-row, X chunked through shared memory, float4 everywhere
template <int COLS, int CHUNK>
__global__ __launch_bounds__(256) void k_gemv4(const float* __restrict__ W,
                                               const float* __restrict__ X,
                                               float* __restrict__ Y, int rows) {
    __shared__ float4 xs[NB][CHUNK / 4];
    const int tid = threadIdx.x;
    const int lane = tid & 31, warp = tid >> 5;
    const int row = blockIdx.x * 8 + warp;
    float a0 = 0.f, a1 = 0.f, a2 = 0.f, a3 = 0.f;
    for (int j0 = 0; j0 < COLS; j0 += CHUNK) {
        __syncthreads();
        for (int i = tid; i < NB * (CHUNK / 4); i += 256) {
            int b = i / (CHUNK / 4), j = i % (CHUNK / 4);
            xs[b][j] = reinterpret_cast<const float4*>(X + (size_t)b * COLS + j0)[j];
        }
        __syncthreads();
        const float4* w4 = reinterpret_cast<const float4*>(W + (size_t)row * COLS + j0);
        #pragma unroll 4
        for (int j = lane; j < CHUNK / 4; j += 32) {
            float4 w = w4[j];
            float4 v0 = xs[0][j], v1 = xs[1][j], v2 = xs[2][j], v3 = xs[3][j];
            a0 += w.x * v0.x + w.y * v0.y + w.z * v0.z + w.w * v0.w;
            a1 += w.x * v1.x + w.y * v1.y + w.z * v1.z + w.w * v1.w;
            a2 += w.x * v2.x + w.y * v2.y + w.z * v2.z + w.w * v2.w;
            a3 += w.x * v3.x + w.y * v3.y + w.z * v3.z + w.w * v3.w;
        }
    }
    #pragma unroll
    for (int o = 16; o; o >>= 1) {
        a0 += __shfl_down_sync(0xffffffffu, a0, o);
        a1 += __shfl_down_sync(0xffffffffu, a1, o);
        a2 += __shfl_down_sync(0xffffffffu, a2, o);
        a3 += __shfl_down_sync(0xffffffffu, a3, o);
    }
    if (lane == 0) {
        Y[0 * rows + row] = a0;
        Y[1 * rows + row] = a1;
        Y[2 * rows + row] = a2;
        Y[3 * rows + row] = a3;
    }
}

// ---------------- q_big[b,h,q] = sum_k q_hk[b,h,k] * w_kc_q[h,k,q] ----------------
__global__ __launch_bounds__(256) void k_qbig(const float* __restrict__ w) {
    int h = blockIdx.x;
    __shared__ float qs[NB][NK];
    for (int i = threadIdx.x; i < NB * NK; i += 256)
        qs[i >> 7][i & 127] = g_qhk[(i >> 7) * (NH * NK) + h * NK + (i & 127)];
    __syncthreads();
    int q = blockIdx.y * 256 + threadIdx.x;
    const float* wp = w + (size_t)h * NK * DCQ + q;
    float a0 = 0.f, a1 = 0.f, a2 = 0.f, a3 = 0.f;
    #pragma unroll 8
    for (int k = 0; k < NK; k++) {
        float wv = wp[(size_t)k * DCQ];
        a0 += qs[0][k] * wv; a1 += qs[1][k] * wv;
        a2 += qs[2][k] * wv; a3 += qs[3][k] * wv;
    }
    g_qbig[0 * (NH * DCQ) + h * DCQ + q] = a0;
    g_qbig[1 * (NH * DCQ) + h * DCQ + q] = a1;
    g_qbig[2 * (NH * DCQ) + h * DCQ + q] = a2;
    g_qbig[3 * (NH * DCQ) + h * DCQ + q] = a3;
}

// ---------------- q_r[b,h,r] = sum_q q_big[b,h,q] * W_qr[h,q,r] ----------------
__global__ __launch_bounds__(256) void k_qr(const float* __restrict__ w) {
    int h = blockIdx.x;
    __shared__ float qs[NB][DCQ];       // 24 KB
    __shared__ float part[4][NB][NR];   // 4 KB
    for (int i = threadIdx.x; i < NB * DCQ; i += 256) {
        int b = i / DCQ, q = i % DCQ;
        qs[b][q] = g_qbig[b * (NH * DCQ) + h * DCQ + q];
    }
    __syncthreads();
    int qc = threadIdx.x >> 6, r = threadIdx.x & 63;
    float a0 = 0.f, a1 = 0.f, a2 = 0.f, a3 = 0.f;
    const float* wp = w + (size_t)h * DCQ * NR;
    int q0 = qc * 384;
    for (int q = q0; q < q0 + 384; q++) {
        float wv = wp[q * NR + r];
        a0 += qs[0][q] * wv; a1 += qs[1][q] * wv;
        a2 += qs[2][q] * wv; a3 += qs[3][q] * wv;
    }
    part[qc][0][r] = a0; part[qc][1][r] = a1;
    part[qc][2][r] = a2; part[qc][3][r] = a3;
    __syncthreads();
    if (qc == 0) {
        #pragma unroll
        for (int b = 0; b < NB; b++) {
            float s = part[0][b][r] + part[1][b][r] + part[2][b][r] + part[3][b][r];
            g_qr[b * (NH * NR) + h * NR + r] = s;
        }
    }
}

// ---------------- v_q[b,d,h] = sum_r W_kr[h,d,r] * q_r[b,h,r] ----------------
__global__ __launch_bounds__(256) void k_vq(const float* __restrict__ w) {
    int h = blockIdx.x;
    __shared__ float qs[NB][NR];
    for (int i = threadIdx.x; i < NB * NR; i += 256)
        qs[i >> 6][i & 63] = g_qr[(i >> 6) * (NH * NR) + h * NR + (i & 63)];
    __syncthreads();
    for (int d = threadIdx.x; d < DC; d += 256) {
        const float4* wp = reinterpret_cast<const float4*>(w + ((size_t)h * DC + d) * NR);
        float a0 = 0.f, a1 = 0.f, a2 = 0.f, a3 = 0.f;
        #pragma unroll
        for (int rv = 0; rv < 16; rv++) {
            float4 wv = wp[rv];
            int r = rv * 4;
            a0 += wv.x * qs[0][r] + wv.y * qs[0][r + 1] + wv.z * qs[0][r + 2] + wv.w * qs[0][r + 3];
            a1 += wv.x * qs[1][r] + wv.y * qs[1][r + 1] + wv.z * qs[1][r + 2] + wv.w * qs[1][r + 3];
            a2 += wv.x * qs[2][r] + wv.y * qs[2][r + 1] + wv.z * qs[2][r + 2] + wv.w * qs[2][r + 3];
            a3 += wv.x * qs[3][r] + wv.y * qs[3][r + 1] + wv.z * qs[3][r + 2] + wv.w * qs[3][r + 3];
        }
        g_vq[0 * (DC * NH) + d * NH + h] = a0;
        g_vq[1 * (DC * NH) + d * NH + h] = a1;
        g_vq[2 * (DC * NH) + d * NH + h] = a2;
        g_vq[3 * (DC * NH) + d * NH + h] = a3;
    }
}

// ---------------- scores[b,h,l] = sum_d kv[b,l,d] * v_q[b,d,h] ----------------
// block: (l-tile 32, b); all 128 h; 4x4 register tile per thread
__global__ __launch_bounds__(256) void k_scores() {
    int b = blockIdx.y, l0 = blockIdx.x * 32;
    __shared__ float sm[10240];   // vqs[64][128] @0, kvs[32][64] @8192; staging reuses
    int tid = threadIdx.x;
    int hq = tid & 31, lq = tid >> 5;
    float acc[4][4];
    #pragma unroll
    for (int i = 0; i < 4; i++)
        #pragma unroll
        for (int j = 0; j < 4; j++) acc[i][j] = 0.f;

    for (int d0 = 0; d0 < DC; d0 += 64) {
        __syncthreads();
        for (int i = tid; i < 8192; i += 256) {
            int d = i >> 7, hh = i & 127;
            sm[i] = g_vq[b * (DC * NH) + (d0 + d) * NH + hh];
        }
        for (int i = tid; i < 2048; i += 256) {
            int l = i >> 6, dd = i & 63;
            sm[8192 + i] = g_kv[((size_t)(b * NL) + l0 + l) * DC + d0 + dd];
        }
        __syncthreads();
        #pragma unroll 4
        for (int dd = 0; dd < 64; dd++) {
            float4 vv = reinterpret_cast<float4*>(sm + dd * 128)[hq];
            #pragma unroll
            for (int j = 0; j < 4; j++) {
                float kvv = sm[8192 + (4 * lq + j) * 64 + dd];
                acc[0][j] += vv.x * kvv;
                acc[1][j] += vv.y * kvv;
                acc[2][j] += vv.z * kvv;
                acc[3][j] += vv.w * kvv;
            }
        }
    }
    __syncthreads();
    #pragma unroll
    for (int i = 0; i < 4; i++)
        #pragma unroll
        for (int j = 0; j < 4; j++)
            sm[(4 * hq + i) * 33 + 4 * lq + j] = acc[i][j];
    __syncthreads();
    for (int i = tid; i < 4096; i += 256) {
        int hh = i >> 5, l = i & 31;
        g_sc[((size_t)(b * NH) + hh) * NL + l0 + l] = sm[hh * 33 + l];
    }
}

// ---------------- softmax over L, in place ----------------
__global__ __launch_bounds__(256) void k_softmax() {
    float* p = g_sc + (size_t)blockIdx.x * NL;
    __shared__ float red[8];
    int tid = threadIdx.x, lane = tid & 31, warp = tid >> 5;
    float m = -1e30f;
    for (int i = tid; i < NL; i += 256) m = fmaxf(m, p[i]);
    #pragma unroll
    for (int o = 16; o; o >>= 1) m = fmaxf(m, __shfl_xor_sync(0xffffffffu, m, o));
    if (lane == 0) red[warp] = m;
    __syncthreads();
    float bm = red[0];
    #pragma unroll
    for (int w = 1; w < 8; w++) bm = fmaxf(bm, red[w]);
    __syncthreads();
    float s = 0.f;
    for (int i = tid; i < NL; i += 256) {
        float e = expf(p[i] - bm);
        p[i] = e;
        s += e;
    }
    #pragma unroll
    for (int o = 16; o; o >>= 1) s += __shfl_xor_sync(0xffffffffu, s, o);
    if (lane == 0) red[warp] = s;
    __syncthreads();
    float bs = red[0];
    #pragma unroll
    for (int w = 1; w < 8; w++) bs += red[w];
    float inv = 1.0f / bs;
    for (int i = tid; i < NL; i += 256) p[i] *= inv;
}

// ---------------- ctx partials: part[ls,b,h,d] = sum_{l in split} attn*kv ----------------
__global__ __launch_bounds__(256) void k_ctx() {
    int b = blockIdx.z;
    int h0 = blockIdx.y * 32;
    int ls = blockIdx.x >> 2;
    int d0 = (blockIdx.x & 3) * 128;
    int lbase = ls * 512;
    __shared__ float sm[5120];   // kvs[32][128] @0 (4096), atts[32][32] @4096 (1024)
    int tid = threadIdx.x;
    int dq = tid & 31, hq = tid >> 5;
    float acc[4][4];
    #pragma unroll
    for (int j = 0; j < 4; j++)
        #pragma unroll
        for (int i = 0; i < 4; i++) acc[j][i] = 0.f;

    for (int lt = 0; lt < 512; lt += 32) {
        __syncthreads();
        for (int i = tid; i < 4096; i += 256) {
            int l = i >> 7, d = i & 127;
            sm[i] = g_kv[((size_t)(b * NL) + lbase + lt + l) * DC + d0 + d];
        }
        for (int i = tid; i < 1024; i += 256) {
            int hh = i >> 5, l = i & 31;
            sm[4096 + i] = g_sc[((size_t)(b * NH) + h0 + hh) * NL + lbase + lt + l];
        }
        __syncthreads();
        #pragma unroll 4
        for (int l = 0; l < 32; l++) {
            float4 kvv = reinterpret_cast<float4*>(sm + l * 128)[dq];
            #pragma unroll
            for (int j = 0; j < 4; j++) {
                float av = sm[4096 + (4 * hq + j) * 32 + l];
                acc[j][0] += av * kvv.x;
                acc[j][1] += av * kvv.y;
                acc[j][2] += av * kvv.z;
                acc[j][3] += av * kvv.w;
            }
        }
    }
    __syncthreads();
    #pragma unroll
    for (int j = 0; j < 4; j++)
        reinterpret_cast<float4*>(sm)[(4 * hq + j) * 33 + dq] =
            make_float4(acc[j][0], acc[j][1], acc[j][2], acc[j][3]);
    __syncthreads();
    for (int i = tid; i < 4096; i += 256) {
        int hh = i >> 7, d = i & 127;
        g_part[(((size_t)ls * NB + b) * NH + h0 + hh) * DC + d0 + d] = sm[hh * 132 + d];
    }
}

__global__ __launch_bounds__(256) void k_ctx_red() {
    int i = blockIdx.x * 256 + threadIdx.x;
    float s = 0.f;
    #pragma unroll
    for (int ls = 0; ls < 8; ls++) s += g_part[(size_t)ls * (NB * NH * DC) + i];
    g_ctxc[i] = s;
}

// ---------------- ctx_lat[b,h,k] = sum_d ctx_c[b,h,d] * w_kc_kv[h,k,d] ----------------
__global__ __launch_bounds__(256) void k_ctxlat(const float* __restrict__ w) {
    int h = blockIdx.x;
    __shared__ float cs[NB][DC];   // 8 KB
    int tid = threadIdx.x;
    for (int i = tid; i < NB * DC; i += 256) {
        int bb = i >> 9, d = i & 511;
        cs[bb][d] = g_ctxc[bb * (NH * DC) + h * DC + d];
    }
    __syncthreads();
    int lane = tid & 31, warp = tid >> 5;
    int k = blockIdx.y * 8 + warp;
    const float* wp = w + ((size_t)h * NK + k) * DC;
    float a0 = 0.f, a1 = 0.f, a2 = 0.f, a3 = 0.f;
    for (int d = lane; d < DC; d += 32) {
        float wv = wp[d];
        a0 += cs[0][d] * wv; a1 += cs[1][d] * wv;
        a2 += cs[2][d] * wv; a3 += cs[3][d] * wv;
    }
    #pragma unroll
    for (int o = 16; o; o >>= 1) {
        a0 += __shfl_down_sync(0xffffffffu, a0, o);
        a1 += __shfl_down_sync(0xffffffffu, a1, o);
        a2 += __shfl_down_sync(0xffffffffu, a2, o);
        a3 += __shfl_down_sync(0xffffffffu, a3, o);
    }
    if (lane == 0) {
        g_ctxlat[0 * (NH * NK) + h * NK + k] = a0;
        g_ctxlat[1 * (NH * NK) + h * NK + k] = a1;
        g_ctxlat[2 * (NH * NK) + h * NK + k] = a2;
        g_ctxlat[3 * (NH * NK) + h * NK + k] = a3;
    }
}

extern "C" void kernel_launch(void* const* d_in, const int* in_sizes, int n_in,
                              void* d_out, int out_size) {
    const float* hidden_q = (const float*)d_in[0];
    const float* kv_c     = (const float*)d_in[1];
    const float* Wq       = (const float*)d_in[2];
    const float* w_kc_q   = (const float*)d_in[3];
    const float* w_kc_kv  = (const float*)d_in[4];
    const float* W_qr     = (const float*)d_in[5];
    const float* W_kr     = (const float*)d_in[6];
    const float* Wout     = (const float*)d_in[7];
    float* out = (float*)d_out;

    void* qhk_p = nullptr;
    void* ctxlat_p = nullptr;
    cudaGetSymbolAddress(&qhk_p, g_qhk);
    cudaGetSymbolAddress(&ctxlat_p, g_ctxlat);

    k_init_invf<<<1, 256>>>();
    k_rope<<<NB * NL, 256>>>(kv_c);

    // query chain
    k_gemv4<DIMQ, 1792><<<(NH * NK) / 8, 256>>>(Wq, hidden_q, (float*)qhk_p, NH * NK);
    k_qbig<<<dim3(NH, DCQ / 256), 256>>>(w_kc_q);
    k_qr<<<NH, 256>>>(W_qr);
    k_vq<<<NH, 256>>>(W_kr);

    // attention
    k_scores<<<dim3(NL / 32, NB), 256>>>();
    k_softmax<<<NB * NH, 256>>>();
    k_ctx<<<dim3(32, NH / 32, NB), 256>>>();
    k_ctx_red<<<(NB * NH * DC) / 256, 256>>>();

    // output chain
    k_ctxlat<<<dim3(NH, NK / 8), 256>>>(w_kc_kv);
    k_gemv4<NH * NK, 2048><<<DIMQ / 8, 256>>>(Wout, (const float*)ctxlat_p, out, DIMQ);
}